// round 16
// baseline (speedup 1.0000x reference)
#include <cuda_runtime.h>
#include <math.h>

// QMixer forward on GB300 — round 16.
// Algebra: M = Wq Wk^T/sqrt(Da); Z folded to FEAT domain (round-13);
// NEW: SH2 folded to FEAT domain too: x_a·W1A2 = F_a·(Wal·W1A2) + bal·W1A2,
// with WW = Wal·W1A2 precomputed and the bal-term folded into w1_b1 (CB).
// 4096 CTAs x 256 thr, 4 pairs/CTA, 4 CTAs/SM.

namespace {

constexpr int NTH   = 256;
constexpr int BSTOT = 16384;
constexpr int GRID  = BSTOT / 4;   // 4096

// ---- smem weight region, float offsets ----
constexpr int OFF_UAL  = 0;        // 32  (Wal·u)
constexpr int OFF_UEN  = 32;       // 16  (Wen·u)
constexpr int OFF_BAL  = 48;       // 64
constexpr int OFF_BEN  = 112;      // 64
constexpr int OFF_BMAL = 176;      // 64  (bal·M)
constexpr int OFF_BMEN = 240;      // 64  (ben·M)
constexpr int OFF_W1B2 = 304;      // 32
constexpr int OFF_WFB2 = 336;      // 32
constexpr int OFF_BCAT = 368;      // 192 [CB | wf_b1 | hb_b | v_b1]
constexpr int OFF_VW2  = 560;      // 32
constexpr int OFF_VB2  = 592;      // 1
constexpr int OFF_BU   = 593;      // 2   [bal·u, ben·u]
constexpr int W_TOT_AL = 608;

// ---- scratch (float offsets) ----
constexpr int S_U1    = W_TOT_AL;
constexpr int S_ZT    = S_U1;            // 5120 [p*1280+c*20+e]
constexpr int S_C     = S_U1;            // 256  [p*64+hu]
constexpr int S_H2    = S_U1 + 256;      // 256
constexpr int S_HBP   = S_U1 + 512;      // 128
constexpr int S_H3    = S_U1 + 640;      // 128
constexpr int S_SH    = S_U1 + 768;      // 2048 [p*512+a*64+hu]
constexpr int S_W1O   = S_U1 + 2816;     // 1024 [p*256+a*32+m]
constexpr int S_AOT   = S_U1 + 4096;     // 256  [d*4+p] (ZT tail, dead after E)
constexpr int S_FEAT  = S_U1 + 5120;     // 1536 [p*384: ally e*32+f | 256+ en e*16+f]
constexpr int S_AQ    = S_FEAT + 1536;   // 32   [p*8+a]
constexpr int S_ENTT  = S_AQ + 32;       // 5120 [p*1280+d*20+e]
constexpr int S_EM    = S_ENTT + 5120;   // 1088 [p*272+i*17+j]
constexpr int S_AMEAN = S_EM + 1088;     // 64
constexpr int S_XU    = S_AMEAN + 64;    // 64
constexpr int SMEM_FLOATS = S_XU + 64;   // 13632

constexpr int SMEM_BYTES  = SMEM_FLOATS * 4;     // 54528 B
static_assert(4 * (SMEM_BYTES + 1024) <= 232448, "4 CTAs must fit with reserve");
static_assert((S_AOT & 3) == 0 && (S_FEAT & 3) == 0, "align");

constexpr float INVS = 0.08838834764831845f;     // 1/sqrt(128)

typedef unsigned long long ull;
__device__ __forceinline__ ull pk(float a, float b) {
    ull r; asm("mov.b64 %0,{%1,%2};" : "=l"(r) : "f"(a), "f"(b)); return r;
}
__device__ __forceinline__ void fma2(ull& acc, ull a, ull b) {
    asm("fma.rn.f32x2 %0,%1,%2,%0;" : "+l"(acc) : "l"(a), "l"(b));
}
__device__ __forceinline__ float2 unpk(ull v) {
    float2 f; asm("mov.b64 {%0,%1},%2;" : "=f"(f.x), "=f"(f.y) : "l"(v)); return f;
}

__device__ __align__(16) float g_M[64 * 64];
__device__ __align__(16) float g_U[64];
__device__ __align__(16) float g_WMAL[32 * 64];  // Wal·M
__device__ __align__(16) float g_WMEN[16 * 64];  // Wen·M
__device__ __align__(16) float g_WW[32 * 64];    // Wal·W1A2
__device__ __align__(16) float g_CB[64];         // w1_b1 + bal·W1A2
__device__ __align__(16) float g_BMAL[64];
__device__ __align__(16) float g_BMEN[64];
__device__ __align__(16) float g_UAL[32];
__device__ __align__(16) float g_UEN[16];
__device__ __align__(16) float g_BU[2];
__device__ __align__(16) float g_WCAT[64 * 192]; // [w1_W1 r0-63 | wf_W1 | hb_W | v_W1]

} // namespace

// ------------- precompute 1: M, u (float4 staging, MLP=8) -------------
__global__ void precompute1_kernel(const float* __restrict__ Wq,
                                   const float* __restrict__ Wk,
                                   const float* __restrict__ bk) {
    __shared__ float sWk[64 * 132];
    __shared__ float sWq[4 * 132];
    int t = threadIdx.x;
    const float4* wk4 = reinterpret_cast<const float4*>(Wk);
    #pragma unroll
    for (int it = 0; it < 8; ++it) {
        int i = t + it * 256;
        float4 v = __ldg(wk4 + i);
        int r = i >> 5, k4 = i & 31;
        *reinterpret_cast<float4*>(&sWk[r * 132 + k4 * 4]) = v;
    }
    if (t < 128) {
        const float4* wq4 = reinterpret_cast<const float4*>(Wq + blockIdx.x * 4 * 128);
        float4 v = __ldg(wq4 + t);
        int r = t >> 5, k4 = t & 31;
        *reinterpret_cast<float4*>(&sWq[r * 132 + k4 * 4]) = v;
    }
    __syncthreads();
    {
        int dd = t >> 6, c = t & 63;
        const float* wq = &sWq[dd * 132];
        const float* wk = &sWk[c * 132];
        float s = 0.f;
        #pragma unroll 8
        for (int k = 0; k < 128; k += 4) {
            float4 a = *reinterpret_cast<const float4*>(&wq[k]);
            float4 b = *reinterpret_cast<const float4*>(&wk[k]);
            s += a.x * b.x + a.y * b.y + a.z * b.z + a.w * b.w;
        }
        g_M[(blockIdx.x * 4 + dd) * 64 + c] = s * INVS;
    }
    if (t < 128) {
        int w = t >> 5, l = t & 31;
        float4 a = *reinterpret_cast<const float4*>(&sWq[w * 132 + l * 4]);
        float4 b = __ldg(reinterpret_cast<const float4*>(bk) + l);
        float s = a.x * b.x + a.y * b.y + a.z * b.z + a.w * b.w;
        #pragma unroll
        for (int off = 16; off > 0; off >>= 1)
            s += __shfl_down_sync(0xffffffffu, s, off);
        if (l == 0) g_U[blockIdx.x * 4 + w] = s * INVS;
    }
}

// ------------- precompute 2: WM/WW folds + WCAT (grid 21) -------------
__global__ void precompute2_kernel(const float* __restrict__ Wal,
                                   const float* __restrict__ bal,
                                   const float* __restrict__ Wen,
                                   const float* __restrict__ ben,
                                   const float* __restrict__ w1W1,
                                   const float* __restrict__ w1b1,
                                   const float* __restrict__ wfW1,
                                   const float* __restrict__ hbW,
                                   const float* __restrict__ vW1) {
    int i = blockIdx.x * 256 + threadIdx.x;   // 0..5375
    const float* W1A2 = w1W1 + 4096;          // rows 64..127
    if (i < 2048) {
        int f = i >> 6, c = i & 63;
        float s = 0.f;
        #pragma unroll 8
        for (int d = 0; d < 64; ++d)
            s = fmaf(Wal[f * 64 + d], g_M[d * 64 + c], s);
        g_WMAL[i] = s;
    } else if (i < 3072) {
        int k = i - 2048;
        int f = k >> 6, c = k & 63;
        float s = 0.f;
        #pragma unroll 8
        for (int d = 0; d < 64; ++d)
            s = fmaf(Wen[f * 64 + d], g_M[d * 64 + c], s);
        g_WMEN[k] = s;
    } else if (i < 5120) {
        int k = i - 3072;
        int f = k >> 6, hu = k & 63;
        float s = 0.f;
        #pragma unroll 8
        for (int d = 0; d < 64; ++d)
            s = fmaf(Wal[f * 64 + d], W1A2[d * 64 + hu], s);
        g_WW[k] = s;
    } else if (i < 5184) {
        int c = i - 5120;
        float s = 0.f;
        #pragma unroll 8
        for (int d = 0; d < 64; ++d)
            s = fmaf(bal[d], g_M[d * 64 + c], s);
        g_BMAL[c] = s;
    } else if (i < 5248) {
        int c = i - 5184;
        float s = 0.f;
        #pragma unroll 8
        for (int d = 0; d < 64; ++d)
            s = fmaf(ben[d], g_M[d * 64 + c], s);
        g_BMEN[c] = s;
    } else if (i < 5312) {
        int hu = i - 5248;
        float s = w1b1[hu];
        #pragma unroll 8
        for (int d = 0; d < 64; ++d)
            s = fmaf(bal[d], W1A2[d * 64 + hu], s);
        g_CB[hu] = s;
    } else if (i < 5344) {
        int f = i - 5312;
        float s = 0.f;
        #pragma unroll 8
        for (int d = 0; d < 64; ++d)
            s = fmaf(Wal[f * 64 + d], g_U[d], s);
        g_UAL[f] = s;
    } else if (i < 5360) {
        int f = i - 5344;
        float s = 0.f;
        #pragma unroll 8
        for (int d = 0; d < 64; ++d)
            s = fmaf(Wen[f * 64 + d], g_U[d], s);
        g_UEN[f] = s;
    } else if (i == 5360) {
        float s = 0.f;
        for (int d = 0; d < 64; ++d) s = fmaf(bal[d], g_U[d], s);
        g_BU[0] = s;
    } else if (i == 5361) {
        float s = 0.f;
        for (int d = 0; d < 64; ++d) s = fmaf(ben[d], g_U[d], s);
        g_BU[1] = s;
    }
    for (int j = i; j < 64 * 192; j += 21 * 256) {
        int f = j / 192, cc = j % 192;
        float v;
        if (cc < 64)       v = w1W1[f * 64 + cc];
        else if (cc < 128) v = wfW1[f * 64 + cc - 64];
        else if (cc < 160) v = hbW[f * 32 + cc - 128];
        else               v = vW1[f * 32 + cc - 160];
        g_WCAT[j] = v;
    }
}

// ------------- main kernel -------------
__global__ void __launch_bounds__(NTH, 4) qmixer_kernel(
    const float* __restrict__ g_aq,     // [B,S,8]
    const float* __restrict__ g_ally,   // [8,B,S,32]
    const float* __restrict__ g_enemy,  // [8,B,S,16]
    const float* __restrict__ g_Wal,  const float* __restrict__ g_bal,
    const float* __restrict__ g_Wen,  const float* __restrict__ g_ben,
    const float* __restrict__ g_w1W2, const float* __restrict__ g_w1b2,
    const float* __restrict__ g_wfb1,
    const float* __restrict__ g_wfW2, const float* __restrict__ g_wfb2,
    const float* __restrict__ g_hbb,
    const float* __restrict__ g_vb1,
    const float* __restrict__ g_vW2,  const float* __restrict__ g_vb2,
    float* __restrict__ out)
{
    extern __shared__ float sm[];
    const int t = threadIdx.x;
    const int gp0 = blockIdx.x * 4;

    // ---- stage smem weights ----
    {
        auto cp4 = [&](int off, const float* src, int n) {
            const float4* s4 = reinterpret_cast<const float4*>(src);
            float4* d4 = reinterpret_cast<float4*>(&sm[off]);
            for (int i = t; i < n / 4; i += NTH) d4[i] = s4[i];
        };
        cp4(OFF_UAL,  g_UAL,  32);
        cp4(OFF_UEN,  g_UEN,  16);
        cp4(OFF_BAL,  g_bal,  64);
        cp4(OFF_BEN,  g_ben,  64);
        cp4(OFF_BMAL, g_BMAL, 64);
        cp4(OFF_BMEN, g_BMEN, 64);
        cp4(OFF_W1B2, g_w1b2, 32);
        cp4(OFF_WFB2, g_wfb2, 32);
        cp4(OFF_VW2,  g_vW2,  32);
        if (t < 192) {
            float b;
            if (t < 64)       b = g_CB[t];
            else if (t < 128) b = g_wfb1[t - 64];
            else if (t < 160) b = g_hbb[t - 128];
            else              b = g_vb1[t - 160];
            sm[OFF_BCAT + t] = b;
        }
        if (t == 0) sm[OFF_VB2] = g_vb2[0];
        if (t < 2)  sm[OFF_BU + t] = g_BU[t];
    }

    // ================= Phase A: load 4 pairs' inputs ========================
    {
        int p = t >> 6, e = (t >> 3) & 7, f4 = t & 7;
        reinterpret_cast<float4*>(&sm[S_FEAT + p * 384 + e * 32])[f4] =
            reinterpret_cast<const float4*>(&g_ally[(e * BSTOT + gp0 + p) * 32])[f4];
        if (t < 128) {
            int pp = t >> 5, ee = (t >> 2) & 7, ff4 = t & 3;
            reinterpret_cast<float4*>(&sm[S_FEAT + pp * 384 + 256 + ee * 16])[ff4] =
                reinterpret_cast<const float4*>(&g_enemy[(ee * BSTOT + gp0 + pp) * 16])[ff4];
        }
        if (t < 32) {
            int pp = t >> 3, a = t & 7;
            sm[S_AQ + pp * 8 + a] = g_aq[(gp0 + pp) * 8 + a];
        }
    }
    __syncthreads();

    // ===== Phase B: embeddings -> ENTT[p][d*20+e]; warp0=ally, warp1=enemy ==
    {
        int p = t >> 6;
        int wv = (t >> 5) & 1;
        int lane = t & 31;               // d and d+32
        const float* FEAT = &sm[S_FEAT + p * 384 + wv * 256];
        float* er = &sm[S_ENTT + p * 1280 + wv * 8];
        float acc[2][8];
        if (wv == 0) {
            float b0 = sm[OFF_BAL + lane], b1 = sm[OFF_BAL + lane + 32];
            #pragma unroll
            for (int e = 0; e < 8; ++e) { acc[0][e] = b0; acc[1][e] = b1; }
            #pragma unroll
            for (int f4 = 0; f4 < 8; ++f4) {
                int f = f4 * 4;
                float wA[4], wB[4];
                #pragma unroll
                for (int j = 0; j < 4; ++j) {
                    wA[j] = __ldg(&g_Wal[(f + j) * 64 + lane]);
                    wB[j] = __ldg(&g_Wal[(f + j) * 64 + lane + 32]);
                }
                #pragma unroll
                for (int e = 0; e < 8; ++e) {
                    float4 x = *reinterpret_cast<const float4*>(&FEAT[e * 32 + f]);
                    acc[0][e] = fmaf(x.x, wA[0], acc[0][e]);
                    acc[0][e] = fmaf(x.y, wA[1], acc[0][e]);
                    acc[0][e] = fmaf(x.z, wA[2], acc[0][e]);
                    acc[0][e] = fmaf(x.w, wA[3], acc[0][e]);
                    acc[1][e] = fmaf(x.x, wB[0], acc[1][e]);
                    acc[1][e] = fmaf(x.y, wB[1], acc[1][e]);
                    acc[1][e] = fmaf(x.z, wB[2], acc[1][e]);
                    acc[1][e] = fmaf(x.w, wB[3], acc[1][e]);
                }
            }
        } else {
            float b0 = sm[OFF_BEN + lane], b1 = sm[OFF_BEN + lane + 32];
            #pragma unroll
            for (int e = 0; e < 8; ++e) { acc[0][e] = b0; acc[1][e] = b1; }
            #pragma unroll
            for (int f4 = 0; f4 < 4; ++f4) {
                int f = f4 * 4;
                float wA[4], wB[4];
                #pragma unroll
                for (int j = 0; j < 4; ++j) {
                    wA[j] = __ldg(&g_Wen[(f + j) * 64 + lane]);
                    wB[j] = __ldg(&g_Wen[(f + j) * 64 + lane + 32]);
                }
                #pragma unroll
                for (int e = 0; e < 8; ++e) {
                    float4 x = *reinterpret_cast<const float4*>(&FEAT[e * 16 + f]);
                    acc[0][e] = fmaf(x.x, wA[0], acc[0][e]);
                    acc[0][e] = fmaf(x.y, wA[1], acc[0][e]);
                    acc[0][e] = fmaf(x.z, wA[2], acc[0][e]);
                    acc[0][e] = fmaf(x.w, wA[3], acc[0][e]);
                    acc[1][e] = fmaf(x.x, wB[0], acc[1][e]);
                    acc[1][e] = fmaf(x.y, wB[1], acc[1][e]);
                    acc[1][e] = fmaf(x.z, wB[2], acc[1][e]);
                    acc[1][e] = fmaf(x.w, wB[3], acc[1][e]);
                }
            }
        }
        #pragma unroll
        for (int d2 = 0; d2 < 2; ++d2) {
            float* row = &er[(lane + 32 * d2) * 20];
            *reinterpret_cast<float4*>(&row[0]) =
                make_float4(acc[d2][0], acc[d2][1], acc[d2][2], acc[d2][3]);
            *reinterpret_cast<float4*>(&row[4]) =
                make_float4(acc[d2][4], acc[d2][5], acc[d2][6], acc[d2][7]);
        }
    }
    // NOTE: no barrier — Znew reads FEAT (written in A), not ENTT.

    // ===== Phase Znew: Z[e][c] = FEAT_e·WM + bM -> ZT[p*1280+c*20+e] ========
    {
        int p = t >> 6;
        int wv = (t >> 5) & 1;           // 0 ally (e0-7), 1 enemy (e8-15)
        int l = t & 31;
        int c0 = 2 * l;
        const float* F = &sm[S_FEAT + p * 384 + wv * 256];
        const int es  = wv ? 16 : 32;
        const int nf4 = wv ? 4 : 8;
        const float* __restrict__ WM = wv ? g_WMEN : g_WMAL;
        int bmoff = wv ? OFF_BMEN : OFF_BMAL;
        ull binit = pk(sm[bmoff + c0], sm[bmoff + c0 + 1]);
        ull acc[8];
        #pragma unroll
        for (int e = 0; e < 8; ++e) acc[e] = binit;
        #pragma unroll 4
        for (int f4 = 0; f4 < nf4; ++f4) {
            int f = f4 * 4;
            ull wmp[4];
            #pragma unroll
            for (int j = 0; j < 4; ++j) {
                float2 w2 = __ldg(reinterpret_cast<const float2*>(&WM[(f + j) * 64 + c0]));
                wmp[j] = pk(w2.x, w2.y);
            }
            #pragma unroll
            for (int e = 0; e < 8; ++e) {
                float4 x = *reinterpret_cast<const float4*>(&F[e * es + f]);
                fma2(acc[e], pk(x.x, x.x), wmp[0]);
                fma2(acc[e], pk(x.y, x.y), wmp[1]);
                fma2(acc[e], pk(x.z, x.z), wmp[2]);
                fma2(acc[e], pk(x.w, x.w), wmp[3]);
            }
        }
        float* Zt = &sm[S_ZT + p * 1280];
        float2 v[8];
        #pragma unroll
        for (int e = 0; e < 8; ++e) v[e] = unpk(acc[e]);
        int eb = wv * 8;
        *reinterpret_cast<float4*>(&Zt[c0 * 20 + eb]) =
            make_float4(v[0].x, v[1].x, v[2].x, v[3].x);
        *reinterpret_cast<float4*>(&Zt[c0 * 20 + eb + 4]) =
            make_float4(v[4].x, v[5].x, v[6].x, v[7].x);
        *reinterpret_cast<float4*>(&Zt[(c0 + 1) * 20 + eb]) =
            make_float4(v[0].y, v[1].y, v[2].y, v[3].y);
        *reinterpret_cast<float4*>(&Zt[(c0 + 1) * 20 + eb + 4]) =
            make_float4(v[4].y, v[5].y, v[6].y, v[7].y);
    }
    __syncthreads();

    // ===== Phase E: E[i][j] = sum_c Z[i,c]·X[j,c]; spare threads: xu ========
    if (t < 128) {
        int p = t >> 5, q = t & 31;
        int i0 = (q >> 3) * 4;        // {0,4,8,12}
        int j0 = (q & 7) * 2;         // {0,2,...,14}
        const float* Zt = &sm[S_ZT + p * 1280];
        const float* X  = &sm[S_ENTT + p * 1280];
        ull acc[4];
        acc[0] = acc[1] = acc[2] = acc[3] = 0ull;
        #pragma unroll 4
        for (int c = 0; c < 64; ++c) {
            float4 z4 = *reinterpret_cast<const float4*>(&Zt[c * 20 + i0]);
            ull x2 = *reinterpret_cast<const ull*>(&X[c * 20 + j0]);
            fma2(acc[0], pk(z4.x, z4.x), x2);
            fma2(acc[1], pk(z4.y, z4.y), x2);
            fma2(acc[2], pk(z4.z, z4.z), x2);
            fma2(acc[3], pk(z4.w, z4.w), x2);
        }
        float* E = &sm[S_EM + p * 272];
        #pragma unroll
        for (int ii = 0; ii < 4; ++ii) {
            float2 v = unpk(acc[ii]);
            E[(i0 + ii) * 17 + j0]     = v.x;
            E[(i0 + ii) * 17 + j0 + 1] = v.y;
        }
    } else if (t < 192) {
        int idx = t - 128;
        int p = idx >> 4, e = idx & 15;
        float s;
        if (e < 8) {
            const float* F = &sm[S_FEAT + p * 384 + e * 32];
            s = sm[OFF_BU];
            #pragma unroll 8
            for (int f = 0; f < 32; ++f)
                s = fmaf(F[f], sm[OFF_UAL + f], s);
        } else {
            const float* F = &sm[S_FEAT + p * 384 + 256 + (e - 8) * 16];
            s = sm[OFF_BU + 1];
            #pragma unroll 8
            for (int f = 0; f < 16; ++f)
                s = fmaf(F[f], sm[OFF_UEN + f], s);
        }
        sm[S_XU + p * 16 + e] = s;
    }
    __syncthreads();

    // ===== softmax over i, per column j; 4-way i split, all 256 threads =====
    {
        int p = t >> 6, j = (t & 63) >> 2, iq = t & 3;
        float* E = &sm[S_EM + p * 272];
        const float* XU = &sm[S_XU + p * 16];
        int ib = iq * 4;
        float c0 = E[(ib    ) * 17 + j] + XU[ib];
        float c1 = E[(ib + 1) * 17 + j] + XU[ib + 1];
        float c2 = E[(ib + 2) * 17 + j] + XU[ib + 2];
        float c3 = E[(ib + 3) * 17 + j] + XU[ib + 3];
        float mx = fmaxf(fmaxf(c0, c1), fmaxf(c2, c3));
        mx = fmaxf(mx, __shfl_xor_sync(0xffffffffu, mx, 1));
        mx = fmaxf(mx, __shfl_xor_sync(0xffffffffu, mx, 2));
        c0 = __expf(c0 - mx);
        c1 = __expf(c1 - mx);
        c2 = __expf(c2 - mx);
        c3 = __expf(c3 - mx);
        float s = c0 + c1 + c2 + c3;
        s += __shfl_xor_sync(0xffffffffu, s, 1);
        s += __shfl_xor_sync(0xffffffffu, s, 2);
        float inv = 1.0f / s;
        E[(ib    ) * 17 + j] = c0 * inv;
        E[(ib + 1) * 17 + j] = c1 * inv;
        E[(ib + 2) * 17 + j] = c2 * inv;
        E[(ib + 3) * 17 + j] = c3 * inv;
    }
    __syncthreads();

    // ===== amean: row sums over j; 4-way j split ============================
    {
        int p = t >> 6, i = (t & 63) >> 2, jq = t & 3;
        const float* Er = &sm[S_EM + p * 272 + i * 17 + jq * 4];
        float s = Er[0] + Er[1] + Er[2] + Er[3];
        s += __shfl_xor_sync(0xffffffffu, s, 1);
        s += __shfl_xor_sync(0xffffffffu, s, 2);
        if (jq == 0) sm[S_AMEAN + p * 16 + i] = s * 0.0625f;
    }
    __syncthreads();

    // ===== attn_out -> AOT[d*4+p] (ZT-tail region, dead after E) ============
    {
        int p = t >> 6, d = t & 63;
        const float* X = &sm[S_ENTT + p * 1280 + d * 20];
        const float* AM = &sm[S_AMEAN + p * 16];
        float4 x0 = *reinterpret_cast<const float4*>(X);
        float4 x1 = *reinterpret_cast<const float4*>(X + 4);
        float4 x2 = *reinterpret_cast<const float4*>(X + 8);
        float4 x3 = *reinterpret_cast<const float4*>(X + 12);
        float4 a0 = *reinterpret_cast<const float4*>(AM);
        float4 a1 = *reinterpret_cast<const float4*>(AM + 4);
        float4 a2 = *reinterpret_cast<const float4*>(AM + 8);
        float4 a3 = *reinterpret_cast<const float4*>(AM + 12);
        float s = x0.x*a0.x + x0.y*a0.y + x0.z*a0.z + x0.w*a0.w
                + x1.x*a1.x + x1.y*a1.y + x1.z*a1.z + x1.w*a1.w
                + x2.x*a2.x + x2.y*a2.y + x2.z*a2.z + x2.w*a2.w
                + x3.x*a3.x + x3.y*a3.y + x3.z*a3.z + x3.w*a3.w;
        sm[S_AOT + d * 4 + p] = s;
    }
    __syncthreads();

    // ===== AOG: all attn_out projections =====================================
    if (t < 192) {
        const int col = t;
        const float* __restrict__ WC = &g_WCAT[col];
        const float* AOT = &sm[S_AOT];
        float a0 = 0.f, a1 = 0.f, a2 = 0.f, a3 = 0.f;
        #pragma unroll 8
        for (int f = 0; f < 64; ++f) {
            float w = __ldg(&WC[f * 192]);
            float4 ao = *reinterpret_cast<const float4*>(&AOT[f * 4]);
            a0 = fmaf(w, ao.x, a0);
            a1 = fmaf(w, ao.y, a1);
            a2 = fmaf(w, ao.z, a2);
            a3 = fmaf(w, ao.w, a3);
        }
        float b = sm[OFF_BCAT + col];
        a0 += b; a1 += b; a2 += b; a3 += b;
        if (col < 64) {
            sm[S_C +   0 + col] = a0;
            sm[S_C +  64 + col] = a1;
            sm[S_C + 128 + col] = a2;
            sm[S_C + 192 + col] = a3;
        } else if (col < 128) {
            int r = col - 64;
            sm[S_H2 +   0 + r] = fmaxf(a0, 0.f);
            sm[S_H2 +  64 + r] = fmaxf(a1, 0.f);
            sm[S_H2 + 128 + r] = fmaxf(a2, 0.f);
            sm[S_H2 + 192 + r] = fmaxf(a3, 0.f);
        } else if (col < 160) {
            int m = col - 128;
            sm[S_HBP +  0 + m] = a0;
            sm[S_HBP + 32 + m] = a1;
            sm[S_HBP + 64 + m] = a2;
            sm[S_HBP + 96 + m] = a3;
        } else {
            int m = col - 160;
            sm[S_H3 +  0 + m] = fmaxf(a0, 0.f);
            sm[S_H3 + 32 + m] = fmaxf(a1, 0.f);
            sm[S_H3 + 64 + m] = fmaxf(a2, 0.f);
            sm[S_H3 + 96 + m] = fmaxf(a3, 0.f);
        }
    }
    __syncthreads();

    // ===== SH2 (FOLDED): SH[a] = relu(C' + F_a·WW); 4 pairs/thread, f<32 ====
    if (t < 128) {
        int ap  = t & 3;                 // agents 2ap, 2ap+1 packed (f32x2)
        int hu0 = (t >> 2) * 2;          // 2 hu per thread
        ull acc[4][2];
        #pragma unroll
        for (int p = 0; p < 4; ++p) {
            float c0 = sm[S_C + p * 64 + hu0];
            float c1 = sm[S_C + p * 64 + hu0 + 1];
            acc[p][0] = pk(c0, c0);
            acc[p][1] = pk(c1, c1);
        }
        const float* __restrict__ W = &g_WW[hu0];
        #pragma unroll 2
        for (int f4 = 0; f4 < 32; f4 += 4) {
            float2 w0 = __ldg(reinterpret_cast<const float2*>(&W[(f4    ) * 64]));
            float2 w1 = __ldg(reinterpret_cast<const float2*>(&W[(f4 + 1) * 64]));
            float2 w2 = __ldg(reinterpret_cast<const float2*>(&W[(f4 + 2) * 64]));
            float2 w3 = __ldg(reinterpret_cast<const float2*>(&W[(f4 + 3) * 64]));
            ull wx0 = pk(w0.x, w0.x), wy0 = pk(w0.y, w0.y);
            ull wx1 = pk(w1.x, w1.x), wy1 = pk(w1.y, w1.y);
            ull wx2 = pk(w2.x, w2.x), wy2 = pk(w2.y, w2.y);
            ull wx3 = pk(w3.x, w3.x), wy3 = pk(w3.y, w3.y);
            #pragma unroll
            for (int p = 0; p < 4; ++p) {
                const float* F = &sm[S_FEAT + p * 384];
                float4 xa = *reinterpret_cast<const float4*>(&F[(2 * ap) * 32 + f4]);
                float4 xb = *reinterpret_cast<const float4*>(&F[(2 * ap + 1) * 32 + f4]);
                ull x0 = pk(xa.x, xb.x), x1 = pk(xa.y, xb.y);
                ull x2 = pk(xa.z, xb.z), x3 = pk(xa.w, xb.w);
                fma2(acc[p][0], x0, wx0); fma2(acc[p][1], x0, wy0);
                fma2(acc[p][0], x1, wx1); fma2(acc[p][1], x1, wy1);
                fma2(acc[p][0], x2, wx2); fma2(acc[p][1], x2, wy2);
                fma2(acc[p][0], x3, wx3); fma2(acc[p][1], x3, wy3);
            }
        }
        #pragma unroll
        for (int p = 0; p < 4; ++p) {
            float* SH = &sm[S_SH + p * 512];
            #pragma unroll
            for (int j = 0; j < 2; ++j) {
                float2 v = unpk(acc[p][j]);
                SH[(2 * ap)     * 64 + hu0 + j] = fmaxf(v.x, 0.f);
                SH[(2 * ap + 1) * 64 + hu0 + j] = fmaxf(v.y, 0.f);
            }
        }
    }
    __syncthreads();

    // ===== W1O: |SH[a] @ w1_W2 + b2|; 4 pairs/thread =========================
    if (t < 64) {
        int a = t >> 3, m0 = (t & 7) * 4;
        ull b0 = pk(sm[OFF_W1B2 + m0],     sm[OFF_W1B2 + m0 + 1]);
        ull b1 = pk(sm[OFF_W1B2 + m0 + 2], sm[OFF_W1B2 + m0 + 3]);
        ull acc[4][2];
        #pragma unroll
        for (int p = 0; p < 4; ++p) { acc[p][0] = b0; acc[p][1] = b1; }
        const float* SHb = &sm[S_SH + a * 64];
        const float* __restrict__ W = &g_w1W2[m0];
        #pragma unroll 2
        for (int k0 = 0; k0 < 64; k0 += 4) {
            float4 s0 = *reinterpret_cast<const float4*>(&SHb[k0]);
            float4 s1 = *reinterpret_cast<const float4*>(&SHb[512 + k0]);
            float4 s2 = *reinterpret_cast<const float4*>(&SHb[1024 + k0]);
            float4 s3 = *reinterpret_cast<const float4*>(&SHb[1536 + k0]);
            #pragma unroll
            for (int j = 0; j < 4; ++j) {
                float4 w4 = __ldg(reinterpret_cast<const float4*>(&W[(k0 + j) * 32]));
                ull wlo = pk(w4.x, w4.y), whi = pk(w4.z, w4.w);
                float v0 = (&s0.x)[j], v1 = (&s1.x)[j];
                float v2 = (&s2.x)[j], v3 = (&s3.x)[j];
                fma2(acc[0][0], pk(v0, v0), wlo); fma2(acc[0][1], pk(v0, v0), whi);
                fma2(acc[1][0], pk(v1, v1), wlo); fma2(acc[1][1], pk(v1, v1), whi);
                fma2(acc[2][0], pk(v2, v2), wlo); fma2(acc[2][1], pk(v2, v2), whi);
                fma2(acc[3][0], pk(v3, v3), wlo); fma2(acc[3][1], pk(v3, v3), whi);
            }
        }
        #pragma unroll
        for (int p = 0; p < 4; ++p) {
            float2 v0 = unpk(acc[p][0]), v1 = unpk(acc[p][1]);
            *reinterpret_cast<float4*>(&sm[S_W1O + p * 256 + a * 32 + m0]) =
                make_float4(fabsf(v0.x), fabsf(v0.y), fabsf(v1.x), fabsf(v1.y));
        }
    }
    __syncthreads();

    // ===== hidden + final (fused); 4 pairs/thread ============================
    if (t < 32) {
        int m = t;
        float hv[4];
        #pragma unroll
        for (int p = 0; p < 4; ++p) {
            const float* AQ  = &sm[S_AQ + p * 8];
            const float* W1O = &sm[S_W1O + p * 256];
            float h = sm[S_HBP + p * 32 + m];
            #pragma unroll
            for (int a = 0; a < 8; ++a)
                h = fmaf(AQ[a], W1O[a * 32 + m], h);
            hv[p] = h > 0.f ? h : expm1f(h);
        }
        float wfb = sm[OFF_WFB2 + m];
        float wf0 = wfb, wf1 = wfb, wf2 = wfb, wf3 = wfb;
        const float* H2b = &sm[S_H2];
        #pragma unroll 4
        for (int k0 = 0; k0 < 64; k0 += 4) {
            float4 h0 = *reinterpret_cast<const float4*>(&H2b[k0]);
            float4 h1 = *reinterpret_cast<const float4*>(&H2b[64 + k0]);
            float4 h2 = *reinterpret_cast<const float4*>(&H2b[128 + k0]);
            float4 h3 = *reinterpret_cast<const float4*>(&H2b[192 + k0]);
            #pragma unroll
            for (int j = 0; j < 4; ++j) {
                float w = __ldg(&g_wfW2[(k0 + j) * 32 + m]);
                wf0 = fmaf((&h0.x)[j], w, wf0);
                wf1 = fmaf((&h1.x)[j], w, wf1);
                wf2 = fmaf((&h2.x)[j], w, wf2);
                wf3 = fmaf((&h3.x)[j], w, wf3);
            }
        }
        float vw2 = sm[OFF_VW2 + m];
        float part[4];
        part[0] = hv[0] * fabsf(wf0) + sm[S_H3 +  0 + m] * vw2;
        part[1] = hv[1] * fabsf(wf1) + sm[S_H3 + 32 + m] * vw2;
        part[2] = hv[2] * fabsf(wf2) + sm[S_H3 + 64 + m] * vw2;
        part[3] = hv[3] * fabsf(wf3) + sm[S_H3 + 96 + m] * vw2;
        #pragma unroll
        for (int p = 0; p < 4; ++p) {
            #pragma unroll
            for (int off = 16; off > 0; off >>= 1)
                part[p] += __shfl_down_sync(0xffffffffu, part[p], off);
        }
        if (m == 0) {
            float vb2 = sm[OFF_VB2];
            out[gp0 + 0] = part[0] + vb2;
            out[gp0 + 1] = part[1] + vb2;
            out[gp0 + 2] = part[2] + vb2;
            out[gp0 + 3] = part[3] + vb2;
        }
    }
}

extern "C" void kernel_launch(void* const* d_in, const int* in_sizes, int n_in,
                              void* d_out, int out_size) {
    (void)in_sizes; (void)n_in; (void)out_size;
    // inputs: 0 aq, 1 ally, 2 enemy, 3 W_al, 4 b_al, 5 W_en, 6 b_en,
    // 7 Wq, 8 bq, 9 Wk, 10 bk, 11 w1_W1, 12 w1_b1, 13 w1_W2, 14 w1_b2,
    // 15 wf_W1, 16 wf_b1, 17 wf_W2, 18 wf_b2, 19 hb_W, 20 hb_b,
    // 21 v_W1, 22 v_b1, 23 v_W2, 24 v_b2
    precompute1_kernel<<<16, 256>>>(
        (const float*)d_in[7], (const float*)d_in[9], (const float*)d_in[10]);
    precompute2_kernel<<<21, 256>>>(
        (const float*)d_in[3],  (const float*)d_in[4],
        (const float*)d_in[5],  (const float*)d_in[6],
        (const float*)d_in[11], (const float*)d_in[12],
        (const float*)d_in[15],
        (const float*)d_in[19], (const float*)d_in[21]);
    cudaFuncSetAttribute(qmixer_kernel,
                         cudaFuncAttributeMaxDynamicSharedMemorySize, SMEM_BYTES);
    qmixer_kernel<<<GRID, NTH, SMEM_BYTES>>>(
        (const float*)d_in[0],  (const float*)d_in[1],  (const float*)d_in[2],
        (const float*)d_in[3],  (const float*)d_in[4],
        (const float*)d_in[5],  (const float*)d_in[6],
        (const float*)d_in[13], (const float*)d_in[14],
        (const float*)d_in[16],
        (const float*)d_in[17], (const float*)d_in[18],
        (const float*)d_in[20],
        (const float*)d_in[22],
        (const float*)d_in[23], (const float*)d_in[24],
        (float*)d_out);
}

// round 17
// speedup vs baseline: 1.1171x; 1.1171x over previous
#include <cuda_runtime.h>
#include <math.h>

// QMixer forward on GB300 — round 17.
// Base = round-15 winner (176.1us) restored verbatim after round-16's SH2-fold
// regression (conflicted FEAT reads). One delta: wf layer-2 GEMV moved onto
// threads 128..255 during the SH2 phase (depends only on H2, ready at AOG),
// shrinking the serial 32-thread tail.

namespace {

constexpr int NTH   = 256;
constexpr int BSTOT = 16384;
constexpr int GRID  = BSTOT / 4;   // 4096

// ---- smem weight region, float offsets ----
constexpr int OFF_UAL  = 0;        // 32  (Wal·u)
constexpr int OFF_UEN  = 32;       // 16  (Wen·u)
constexpr int OFF_BAL  = 48;       // 64
constexpr int OFF_BEN  = 112;      // 64
constexpr int OFF_BMAL = 176;      // 64  (bal·M)
constexpr int OFF_BMEN = 240;      // 64  (ben·M)
constexpr int OFF_W1B2 = 304;      // 32
constexpr int OFF_WFB2 = 336;      // 32
constexpr int OFF_BCAT = 368;      // 192 [w1_b1 | wf_b1 | hb_b | v_b1]
constexpr int OFF_VW2  = 560;      // 32
constexpr int OFF_VB2  = 592;      // 1
constexpr int OFF_BU   = 593;      // 2   [bal·u, ben·u]
constexpr int W_TOT_AL = 608;

// ---- scratch (float offsets) ----
constexpr int S_U1    = W_TOT_AL;
constexpr int S_ZT    = S_U1;            // 5120 [p*1280+c*20+e]
constexpr int S_C     = S_U1;            // 256  [p*64+hu]
constexpr int S_H2    = S_U1 + 256;      // 256
constexpr int S_HBP   = S_U1 + 512;      // 128
constexpr int S_H3    = S_U1 + 640;      // 128
constexpr int S_SH    = S_U1 + 768;      // 2048 [p*512+a*64+hu]
constexpr int S_W1O   = S_U1 + 2816;     // 1024 [p*256+a*32+m]
constexpr int S_AOT   = S_U1 + 4096;     // 256  [d*4+p] (ZT tail, dead after E)
constexpr int S_FEAT  = S_U1 + 5120;     // 1536 [p*384: ally e*32+f | 256+ en e*16+f]
constexpr int S_AQ    = S_FEAT + 1536;   // 32   [p*8+a]
constexpr int S_ENTT  = S_AQ + 32;       // 5120 [p*1280+d*20+e]
constexpr int S_EM    = S_ENTT + 5120;   // 1088 [p*272+i*17+j]
constexpr int S_AMEAN = S_EM + 1088;     // 64
constexpr int S_XU    = S_AMEAN + 64;    // 64
constexpr int S_WF    = S_XU + 64;       // 128  [p*32+m] = |wf| (overlap buffer)
constexpr int SMEM_FLOATS = S_WF + 128;  // 13760

constexpr int SMEM_BYTES  = SMEM_FLOATS * 4;     // 55040 B
static_assert(4 * (SMEM_BYTES + 1024) <= 232448, "4 CTAs must fit with reserve");
static_assert((S_AOT & 3) == 0 && (S_FEAT & 3) == 0, "align");

constexpr float INVS = 0.08838834764831845f;     // 1/sqrt(128)

typedef unsigned long long ull;
__device__ __forceinline__ ull pk(float a, float b) {
    ull r; asm("mov.b64 %0,{%1,%2};" : "=l"(r) : "f"(a), "f"(b)); return r;
}
__device__ __forceinline__ void fma2(ull& acc, ull a, ull b) {
    asm("fma.rn.f32x2 %0,%1,%2,%0;" : "+l"(acc) : "l"(a), "l"(b));
}
__device__ __forceinline__ float2 unpk(ull v) {
    float2 f; asm("mov.b64 {%0,%1},%2;" : "=f"(f.x), "=f"(f.y) : "l"(v)); return f;
}

__device__ __align__(16) float g_M[64 * 64];
__device__ __align__(16) float g_U[64];
__device__ __align__(16) float g_WMAL[32 * 64];  // Wal·M
__device__ __align__(16) float g_WMEN[16 * 64];  // Wen·M
__device__ __align__(16) float g_BMAL[64];
__device__ __align__(16) float g_BMEN[64];
__device__ __align__(16) float g_UAL[32];
__device__ __align__(16) float g_UEN[16];
__device__ __align__(16) float g_BU[2];
__device__ __align__(16) float g_WCAT[64 * 192]; // [w1_W1 r0-63 | wf_W1 | hb_W | v_W1]

} // namespace

// ------------- precompute 1: M, u (float4 staging, MLP=8) -------------
__global__ void precompute1_kernel(const float* __restrict__ Wq,
                                   const float* __restrict__ Wk,
                                   const float* __restrict__ bk) {
    __shared__ float sWk[64 * 132];
    __shared__ float sWq[4 * 132];
    int t = threadIdx.x;
    const float4* wk4 = reinterpret_cast<const float4*>(Wk);
    #pragma unroll
    for (int it = 0; it < 8; ++it) {
        int i = t + it * 256;
        float4 v = __ldg(wk4 + i);
        int r = i >> 5, k4 = i & 31;
        *reinterpret_cast<float4*>(&sWk[r * 132 + k4 * 4]) = v;
    }
    if (t < 128) {
        const float4* wq4 = reinterpret_cast<const float4*>(Wq + blockIdx.x * 4 * 128);
        float4 v = __ldg(wq4 + t);
        int r = t >> 5, k4 = t & 31;
        *reinterpret_cast<float4*>(&sWq[r * 132 + k4 * 4]) = v;
    }
    __syncthreads();
    {
        int dd = t >> 6, c = t & 63;
        const float* wq = &sWq[dd * 132];
        const float* wk = &sWk[c * 132];
        float s = 0.f;
        #pragma unroll 8
        for (int k = 0; k < 128; k += 4) {
            float4 a = *reinterpret_cast<const float4*>(&wq[k]);
            float4 b = *reinterpret_cast<const float4*>(&wk[k]);
            s += a.x * b.x + a.y * b.y + a.z * b.z + a.w * b.w;
        }
        g_M[(blockIdx.x * 4 + dd) * 64 + c] = s * INVS;
    }
    if (t < 128) {
        int w = t >> 5, l = t & 31;
        float4 a = *reinterpret_cast<const float4*>(&sWq[w * 132 + l * 4]);
        float4 b = __ldg(reinterpret_cast<const float4*>(bk) + l);
        float s = a.x * b.x + a.y * b.y + a.z * b.z + a.w * b.w;
        #pragma unroll
        for (int off = 16; off > 0; off >>= 1)
            s += __shfl_down_sync(0xffffffffu, s, off);
        if (l == 0) g_U[blockIdx.x * 4 + w] = s * INVS;
    }
}

// ------------- precompute 2: WM folds + WCAT -------------
__global__ void precompute2_kernel(const float* __restrict__ Wal,
                                   const float* __restrict__ bal,
                                   const float* __restrict__ Wen,
                                   const float* __restrict__ ben,
                                   const float* __restrict__ w1W1,
                                   const float* __restrict__ wfW1,
                                   const float* __restrict__ hbW,
                                   const float* __restrict__ vW1) {
    int i = blockIdx.x * 256 + threadIdx.x;   // 0..4095
    if (i < 2048) {
        int f = i >> 6, c = i & 63;
        float s = 0.f;
        #pragma unroll 8
        for (int d = 0; d < 64; ++d)
            s = fmaf(Wal[f * 64 + d], g_M[d * 64 + c], s);
        g_WMAL[i] = s;
    } else if (i < 3072) {
        int k = i - 2048;
        int f = k >> 6, c = k & 63;
        float s = 0.f;
        #pragma unroll 8
        for (int d = 0; d < 64; ++d)
            s = fmaf(Wen[f * 64 + d], g_M[d * 64 + c], s);
        g_WMEN[k] = s;
    } else if (i < 3136) {
        int c = i - 3072;
        float s = 0.f;
        #pragma unroll 8
        for (int d = 0; d < 64; ++d)
            s = fmaf(bal[d], g_M[d * 64 + c], s);
        g_BMAL[c] = s;
    } else if (i < 3200) {
        int c = i - 3136;
        float s = 0.f;
        #pragma unroll 8
        for (int d = 0; d < 64; ++d)
            s = fmaf(ben[d], g_M[d * 64 + c], s);
        g_BMEN[c] = s;
    } else if (i < 3232) {
        int f = i - 3200;
        float s = 0.f;
        #pragma unroll 8
        for (int d = 0; d < 64; ++d)
            s = fmaf(Wal[f * 64 + d], g_U[d], s);
        g_UAL[f] = s;
    } else if (i < 3248) {
        int f = i - 3232;
        float s = 0.f;
        #pragma unroll 8
        for (int d = 0; d < 64; ++d)
            s = fmaf(Wen[f * 64 + d], g_U[d], s);
        g_UEN[f] = s;
    } else if (i == 3248) {
        float s = 0.f;
        for (int d = 0; d < 64; ++d) s = fmaf(bal[d], g_U[d], s);
        g_BU[0] = s;
    } else if (i == 3249) {
        float s = 0.f;
        for (int d = 0; d < 64; ++d) s = fmaf(ben[d], g_U[d], s);
        g_BU[1] = s;
    }
    for (int j = i; j < 64 * 192; j += 16 * 256) {
        int f = j / 192, cc = j % 192;
        float v;
        if (cc < 64)       v = w1W1[f * 64 + cc];
        else if (cc < 128) v = wfW1[f * 64 + cc - 64];
        else if (cc < 160) v = hbW[f * 32 + cc - 128];
        else               v = vW1[f * 32 + cc - 160];
        g_WCAT[j] = v;
    }
}

// ------------- main kernel -------------
__global__ void __launch_bounds__(NTH, 4) qmixer_kernel(
    const float* __restrict__ g_aq,     // [B,S,8]
    const float* __restrict__ g_ally,   // [8,B,S,32]
    const float* __restrict__ g_enemy,  // [8,B,S,16]
    const float* __restrict__ g_Wal,  const float* __restrict__ g_bal,
    const float* __restrict__ g_Wen,  const float* __restrict__ g_ben,
    const float* __restrict__ g_w1W1, const float* __restrict__ g_w1b1,
    const float* __restrict__ g_w1W2, const float* __restrict__ g_w1b2,
    const float* __restrict__ g_wfb1,
    const float* __restrict__ g_wfW2, const float* __restrict__ g_wfb2,
    const float* __restrict__ g_hbb,
    const float* __restrict__ g_vb1,
    const float* __restrict__ g_vW2,  const float* __restrict__ g_vb2,
    float* __restrict__ out)
{
    extern __shared__ float sm[];
    const int t = threadIdx.x;
    const int gp0 = blockIdx.x * 4;
    const float* __restrict__ g_W1A2 = g_w1W1 + 4096;   // rows 64..127

    // ---- stage smem weights ----
    {
        auto cp4 = [&](int off, const float* src, int n) {
            const float4* s4 = reinterpret_cast<const float4*>(src);
            float4* d4 = reinterpret_cast<float4*>(&sm[off]);
            for (int i = t; i < n / 4; i += NTH) d4[i] = s4[i];
        };
        cp4(OFF_UAL,  g_UAL,  32);
        cp4(OFF_UEN,  g_UEN,  16);
        cp4(OFF_BAL,  g_bal,  64);
        cp4(OFF_BEN,  g_ben,  64);
        cp4(OFF_BMAL, g_BMAL, 64);
        cp4(OFF_BMEN, g_BMEN, 64);
        cp4(OFF_W1B2, g_w1b2, 32);
        cp4(OFF_WFB2, g_wfb2, 32);
        cp4(OFF_VW2,  g_vW2,  32);
        if (t < 192) {
            float b;
            if (t < 64)       b = g_w1b1[t];
            else if (t < 128) b = g_wfb1[t - 64];
            else if (t < 160) b = g_hbb[t - 128];
            else              b = g_vb1[t - 160];
            sm[OFF_BCAT + t] = b;
        }
        if (t == 0) sm[OFF_VB2] = g_vb2[0];
        if (t < 2)  sm[OFF_BU + t] = g_BU[t];
    }

    // ================= Phase A: load 4 pairs' inputs ========================
    {
        int p = t >> 6, e = (t >> 3) & 7, f4 = t & 7;
        reinterpret_cast<float4*>(&sm[S_FEAT + p * 384 + e * 32])[f4] =
            reinterpret_cast<const float4*>(&g_ally[(e * BSTOT + gp0 + p) * 32])[f4];
        if (t < 128) {
            int pp = t >> 5, ee = (t >> 2) & 7, ff4 = t & 3;
            reinterpret_cast<float4*>(&sm[S_FEAT + pp * 384 + 256 + ee * 16])[ff4] =
                reinterpret_cast<const float4*>(&g_enemy[(ee * BSTOT + gp0 + pp) * 16])[ff4];
        }
        if (t < 32) {
            int pp = t >> 3, a = t & 7;
            sm[S_AQ + pp * 8 + a] = g_aq[(gp0 + pp) * 8 + a];
        }
    }
    __syncthreads();

    // ===== Phase B: embeddings -> ENTT[p][d*20+e]; warp0=ally, warp1=enemy ==
    {
        int p = t >> 6;
        int wv = (t >> 5) & 1;
        int lane = t & 31;               // d and d+32
        const float* FEAT = &sm[S_FEAT + p * 384 + wv * 256];
        float* er = &sm[S_ENTT + p * 1280 + wv * 8];
        float acc[2][8];
        if (wv == 0) {
            float b0 = sm[OFF_BAL + lane], b1 = sm[OFF_BAL + lane + 32];
            #pragma unroll
            for (int e = 0; e < 8; ++e) { acc[0][e] = b0; acc[1][e] = b1; }
            #pragma unroll
            for (int f4 = 0; f4 < 8; ++f4) {
                int f = f4 * 4;
                float wA[4], wB[4];
                #pragma unroll
                for (int j = 0; j < 4; ++j) {
                    wA[j] = __ldg(&g_Wal[(f + j) * 64 + lane]);
                    wB[j] = __ldg(&g_Wal[(f + j) * 64 + lane + 32]);
                }
                #pragma unroll
                for (int e = 0; e < 8; ++e) {
                    float4 x = *reinterpret_cast<const float4*>(&FEAT[e * 32 + f]);
                    acc[0][e] = fmaf(x.x, wA[0], acc[0][e]);
                    acc[0][e] = fmaf(x.y, wA[1], acc[0][e]);
                    acc[0][e] = fmaf(x.z, wA[2], acc[0][e]);
                    acc[0][e] = fmaf(x.w, wA[3], acc[0][e]);
                    acc[1][e] = fmaf(x.x, wB[0], acc[1][e]);
                    acc[1][e] = fmaf(x.y, wB[1], acc[1][e]);
                    acc[1][e] = fmaf(x.z, wB[2], acc[1][e]);
                    acc[1][e] = fmaf(x.w, wB[3], acc[1][e]);
                }
            }
        } else {
            float b0 = sm[OFF_BEN + lane], b1 = sm[OFF_BEN + lane + 32];
            #pragma unroll
            for (int e = 0; e < 8; ++e) { acc[0][e] = b0; acc[1][e] = b1; }
            #pragma unroll
            for (int f4 = 0; f4 < 4; ++f4) {
                int f = f4 * 4;
                float wA[4], wB[4];
                #pragma unroll
                for (int j = 0; j < 4; ++j) {
                    wA[j] = __ldg(&g_Wen[(f + j) * 64 + lane]);
                    wB[j] = __ldg(&g_Wen[(f + j) * 64 + lane + 32]);
                }
                #pragma unroll
                for (int e = 0; e < 8; ++e) {
                    float4 x = *reinterpret_cast<const float4*>(&FEAT[e * 16 + f]);
                    acc[0][e] = fmaf(x.x, wA[0], acc[0][e]);
                    acc[0][e] = fmaf(x.y, wA[1], acc[0][e]);
                    acc[0][e] = fmaf(x.z, wA[2], acc[0][e]);
                    acc[0][e] = fmaf(x.w, wA[3], acc[0][e]);
                    acc[1][e] = fmaf(x.x, wB[0], acc[1][e]);
                    acc[1][e] = fmaf(x.y, wB[1], acc[1][e]);
                    acc[1][e] = fmaf(x.z, wB[2], acc[1][e]);
                    acc[1][e] = fmaf(x.w, wB[3], acc[1][e]);
                }
            }
        }
        #pragma unroll
        for (int d2 = 0; d2 < 2; ++d2) {
            float* row = &er[(lane + 32 * d2) * 20];
            *reinterpret_cast<float4*>(&row[0]) =
                make_float4(acc[d2][0], acc[d2][1], acc[d2][2], acc[d2][3]);
            *reinterpret_cast<float4*>(&row[4]) =
                make_float4(acc[d2][4], acc[d2][5], acc[d2][6], acc[d2][7]);
        }
    }
    // NOTE: no barrier — Znew reads FEAT (written in A), not ENTT.

    // ===== Phase Znew: Z[e][c] = FEAT_e·WM + bM -> ZT[p*1280+c*20+e] ========
    {
        int p = t >> 6;
        int wv = (t >> 5) & 1;           // 0 ally (e0-7), 1 enemy (e8-15)
        int l = t & 31;
        int c0 = 2 * l;
        const float* F = &sm[S_FEAT + p * 384 + wv * 256];
        const int es  = wv ? 16 : 32;
        const int nf4 = wv ? 4 : 8;
        const float* __restrict__ WM = wv ? g_WMEN : g_WMAL;
        int bmoff = wv ? OFF_BMEN : OFF_BMAL;
        ull binit = pk(sm[bmoff + c0], sm[bmoff + c0 + 1]);
        ull acc[8];
        #pragma unroll
        for (int e = 0; e < 8; ++e) acc[e] = binit;
        #pragma unroll 4
        for (int f4 = 0; f4 < nf4; ++f4) {
            int f = f4 * 4;
            ull wmp[4];
            #pragma unroll
            for (int j = 0; j < 4; ++j) {
                float2 w2 = __ldg(reinterpret_cast<const float2*>(&WM[(f + j) * 64 + c0]));
                wmp[j] = pk(w2.x, w2.y);
            }
            #pragma unroll
            for (int e = 0; e < 8; ++e) {
                float4 x = *reinterpret_cast<const float4*>(&F[e * es + f]);
                fma2(acc[e], pk(x.x, x.x), wmp[0]);
                fma2(acc[e], pk(x.y, x.y), wmp[1]);
                fma2(acc[e], pk(x.z, x.z), wmp[2]);
                fma2(acc[e], pk(x.w, x.w), wmp[3]);
            }
        }
        float* Zt = &sm[S_ZT + p * 1280];
        float2 v[8];
        #pragma unroll
        for (int e = 0; e < 8; ++e) v[e] = unpk(acc[e]);
        int eb = wv * 8;
        *reinterpret_cast<float4*>(&Zt[c0 * 20 + eb]) =
            make_float4(v[0].x, v[1].x, v[2].x, v[3].x);
        *reinterpret_cast<float4*>(&Zt[c0 * 20 + eb + 4]) =
            make_float4(v[4].x, v[5].x, v[6].x, v[7].x);
        *reinterpret_cast<float4*>(&Zt[(c0 + 1) * 20 + eb]) =
            make_float4(v[0].y, v[1].y, v[2].y, v[3].y);
        *reinterpret_cast<float4*>(&Zt[(c0 + 1) * 20 + eb + 4]) =
            make_float4(v[4].y, v[5].y, v[6].y, v[7].y);
    }
    __syncthreads();

    // ===== Phase E: E[i][j] = sum_c Z[i,c]·X[j,c]; spare threads: xu ========
    if (t < 128) {
        int p = t >> 5, q = t & 31;
        int i0 = (q >> 3) * 4;        // {0,4,8,12}
        int j0 = (q & 7) * 2;         // {0,2,...,14}
        const float* Zt = &sm[S_ZT + p * 1280];
        const float* X  = &sm[S_ENTT + p * 1280];
        ull acc[4];
        acc[0] = acc[1] = acc[2] = acc[3] = 0ull;
        #pragma unroll 4
        for (int c = 0; c < 64; ++c) {
            float4 z4 = *reinterpret_cast<const float4*>(&Zt[c * 20 + i0]);
            ull x2 = *reinterpret_cast<const ull*>(&X[c * 20 + j0]);
            fma2(acc[0], pk(z4.x, z4.x), x2);
            fma2(acc[1], pk(z4.y, z4.y), x2);
            fma2(acc[2], pk(z4.z, z4.z), x2);
            fma2(acc[3], pk(z4.w, z4.w), x2);
        }
        float* E = &sm[S_EM + p * 272];
        #pragma unroll
        for (int ii = 0; ii < 4; ++ii) {
            float2 v = unpk(acc[ii]);
            E[(i0 + ii) * 17 + j0]     = v.x;
            E[(i0 + ii) * 17 + j0 + 1] = v.y;
        }
    } else if (t < 192) {
        int idx = t - 128;
        int p = idx >> 4, e = idx & 15;
        float s;
        if (e < 8) {
            const float* F = &sm[S_FEAT + p * 384 + e * 32];
            s = sm[OFF_BU];
            #pragma unroll 8
            for (int f = 0; f < 32; ++f)
                s = fmaf(F[f], sm[OFF_UAL + f], s);
        } else {
            const float* F = &sm[S_FEAT + p * 384 + 256 + (e - 8) * 16];
            s = sm[OFF_BU + 1];
            #pragma unroll 8
            for (int f = 0; f < 16; ++f)
                s = fmaf(F[f], sm[OFF_UEN + f], s);
        }
        sm[S_XU + p * 16 + e] = s;
    }
    __syncthreads();

    // ===== softmax over i, per column j; 4-way i split, all 256 threads =====
    {
        int p = t >> 6, j = (t & 63) >> 2, iq = t & 3;
        float* E = &sm[S_EM + p * 272];
        const float* XU = &sm[S_XU + p * 16];
        int ib = iq * 4;
        float c0 = E[(ib    ) * 17 + j] + XU[ib];
        float c1 = E[(ib + 1) * 17 + j] + XU[ib + 1];
        float c2 = E[(ib + 2) * 17 + j] + XU[ib + 2];
        float c3 = E[(ib + 3) * 17 + j] + XU[ib + 3];
        float mx = fmaxf(fmaxf(c0, c1), fmaxf(c2, c3));
        mx = fmaxf(mx, __shfl_xor_sync(0xffffffffu, mx, 1));
        mx = fmaxf(mx, __shfl_xor_sync(0xffffffffu, mx, 2));
        c0 = __expf(c0 - mx);
        c1 = __expf(c1 - mx);
        c2 = __expf(c2 - mx);
        c3 = __expf(c3 - mx);
        float s = c0 + c1 + c2 + c3;
        s += __shfl_xor_sync(0xffffffffu, s, 1);
        s += __shfl_xor_sync(0xffffffffu, s, 2);
        float inv = 1.0f / s;
        E[(ib    ) * 17 + j] = c0 * inv;
        E[(ib + 1) * 17 + j] = c1 * inv;
        E[(ib + 2) * 17 + j] = c2 * inv;
        E[(ib + 3) * 17 + j] = c3 * inv;
    }
    __syncthreads();

    // ===== amean: row sums over j; 4-way j split ============================
    {
        int p = t >> 6, i = (t & 63) >> 2, jq = t & 3;
        const float* Er = &sm[S_EM + p * 272 + i * 17 + jq * 4];
        float s = Er[0] + Er[1] + Er[2] + Er[3];
        s += __shfl_xor_sync(0xffffffffu, s, 1);
        s += __shfl_xor_sync(0xffffffffu, s, 2);
        if (jq == 0) sm[S_AMEAN + p * 16 + i] = s * 0.0625f;
    }
    __syncthreads();

    // ===== attn_out -> AOT[d*4+p] (ZT-tail region, dead after E) ============
    {
        int p = t >> 6, d = t & 63;
        const float* X = &sm[S_ENTT + p * 1280 + d * 20];
        const float* AM = &sm[S_AMEAN + p * 16];
        float4 x0 = *reinterpret_cast<const float4*>(X);
        float4 x1 = *reinterpret_cast<const float4*>(X + 4);
        float4 x2 = *reinterpret_cast<const float4*>(X + 8);
        float4 x3 = *reinterpret_cast<const float4*>(X + 12);
        float4 a0 = *reinterpret_cast<const float4*>(AM);
        float4 a1 = *reinterpret_cast<const float4*>(AM + 4);
        float4 a2 = *reinterpret_cast<const float4*>(AM + 8);
        float4 a3 = *reinterpret_cast<const float4*>(AM + 12);
        float s = x0.x*a0.x + x0.y*a0.y + x0.z*a0.z + x0.w*a0.w
                + x1.x*a1.x + x1.y*a1.y + x1.z*a1.z + x1.w*a1.w
                + x2.x*a2.x + x2.y*a2.y + x2.z*a2.z + x2.w*a2.w
                + x3.x*a3.x + x3.y*a3.y + x3.z*a3.z + x3.w*a3.w;
        sm[S_AOT + d * 4 + p] = s;
    }
    __syncthreads();

    // ===== AOG: all attn_out projections =====================================
    if (t < 192) {
        const int col = t;
        const float* __restrict__ WC = &g_WCAT[col];
        const float* AOT = &sm[S_AOT];
        float a0 = 0.f, a1 = 0.f, a2 = 0.f, a3 = 0.f;
        #pragma unroll 8
        for (int f = 0; f < 64; ++f) {
            float w = __ldg(&WC[f * 192]);
            float4 ao = *reinterpret_cast<const float4*>(&AOT[f * 4]);
            a0 = fmaf(w, ao.x, a0);
            a1 = fmaf(w, ao.y, a1);
            a2 = fmaf(w, ao.z, a2);
            a3 = fmaf(w, ao.w, a3);
        }
        float b = sm[OFF_BCAT + col];
        a0 += b; a1 += b; a2 += b; a3 += b;
        if (col < 64) {
            sm[S_C +   0 + col] = a0;
            sm[S_C +  64 + col] = a1;
            sm[S_C + 128 + col] = a2;
            sm[S_C + 192 + col] = a3;
        } else if (col < 128) {
            int r = col - 64;
            sm[S_H2 +   0 + r] = fmaxf(a0, 0.f);
            sm[S_H2 +  64 + r] = fmaxf(a1, 0.f);
            sm[S_H2 + 128 + r] = fmaxf(a2, 0.f);
            sm[S_H2 + 192 + r] = fmaxf(a3, 0.f);
        } else if (col < 160) {
            int m = col - 128;
            sm[S_HBP +  0 + m] = a0;
            sm[S_HBP + 32 + m] = a1;
            sm[S_HBP + 64 + m] = a2;
            sm[S_HBP + 96 + m] = a3;
        } else {
            int m = col - 160;
            sm[S_H3 +  0 + m] = fmaxf(a0, 0.f);
            sm[S_H3 + 32 + m] = fmaxf(a1, 0.f);
            sm[S_H3 + 64 + m] = fmaxf(a2, 0.f);
            sm[S_H3 + 96 + m] = fmaxf(a3, 0.f);
        }
    }
    __syncthreads();

    // ===== SH2 (t<128) || wf layer-2 (t>=128, overlapped) ===================
    if (t < 128) {
        int ap  = t & 3;                 // agents 2ap, 2ap+1 packed (f32x2)
        int hu0 = (t >> 2) * 2;          // 2 hu per thread
        ull acc[4][2];
        #pragma unroll
        for (int p = 0; p < 4; ++p) {
            float c0 = sm[S_C + p * 64 + hu0];
            float c1 = sm[S_C + p * 64 + hu0 + 1];
            acc[p][0] = pk(c0, c0);
            acc[p][1] = pk(c1, c1);
        }
        const float* __restrict__ W = &g_W1A2[hu0];
        const float* X = &sm[S_ENTT + 2 * ap];
        #pragma unroll 4
        for (int f = 0; f < 64; ++f) {
            float2 w2 = __ldg(reinterpret_cast<const float2*>(&W[f * 64]));
            ull wx = pk(w2.x, w2.x), wy = pk(w2.y, w2.y);
            ull xp0 = *reinterpret_cast<const ull*>(&X[f * 20]);
            ull xp1 = *reinterpret_cast<const ull*>(&X[1280 + f * 20]);
            ull xp2 = *reinterpret_cast<const ull*>(&X[2560 + f * 20]);
            ull xp3 = *reinterpret_cast<const ull*>(&X[3840 + f * 20]);
            fma2(acc[0][0], xp0, wx); fma2(acc[0][1], xp0, wy);
            fma2(acc[1][0], xp1, wx); fma2(acc[1][1], xp1, wy);
            fma2(acc[2][0], xp2, wx); fma2(acc[2][1], xp2, wy);
            fma2(acc[3][0], xp3, wx); fma2(acc[3][1], xp3, wy);
        }
        #pragma unroll
        for (int p = 0; p < 4; ++p) {
            float* SH = &sm[S_SH + p * 512];
            #pragma unroll
            for (int j = 0; j < 2; ++j) {
                float2 v = unpk(acc[p][j]);
                SH[(2 * ap)     * 64 + hu0 + j] = fmaxf(v.x, 0.f);
                SH[(2 * ap + 1) * 64 + hu0 + j] = fmaxf(v.y, 0.f);
            }
        }
    } else {
        // wf[p][m] = |wf_b2[m] + sum_k H2[p][k] * wfW2[k][m]|  (needs H2 only)
        int idx = t - 128;               // p*32 + m
        int p = idx >> 5, m = idx & 31;
        const float* H2 = &sm[S_H2 + p * 64];
        float wf = sm[OFF_WFB2 + m];
        #pragma unroll 4
        for (int k0 = 0; k0 < 64; k0 += 4) {
            float4 h4 = *reinterpret_cast<const float4*>(&H2[k0]);
            wf = fmaf(h4.x, __ldg(&g_wfW2[(k0    ) * 32 + m]), wf);
            wf = fmaf(h4.y, __ldg(&g_wfW2[(k0 + 1) * 32 + m]), wf);
            wf = fmaf(h4.z, __ldg(&g_wfW2[(k0 + 2) * 32 + m]), wf);
            wf = fmaf(h4.w, __ldg(&g_wfW2[(k0 + 3) * 32 + m]), wf);
        }
        sm[S_WF + idx] = fabsf(wf);
    }
    __syncthreads();

    // ===== W1O: |SH[a] @ w1_W2 + b2|; 4 pairs/thread =========================
    if (t < 64) {
        int a = t >> 3, m0 = (t & 7) * 4;
        ull b0 = pk(sm[OFF_W1B2 + m0],     sm[OFF_W1B2 + m0 + 1]);
        ull b1 = pk(sm[OFF_W1B2 + m0 + 2], sm[OFF_W1B2 + m0 + 3]);
        ull acc[4][2];
        #pragma unroll
        for (int p = 0; p < 4; ++p) { acc[p][0] = b0; acc[p][1] = b1; }
        const float* SHb = &sm[S_SH + a * 64];
        const float* __restrict__ W = &g_w1W2[m0];
        #pragma unroll 2
        for (int k0 = 0; k0 < 64; k0 += 4) {
            float4 s0 = *reinterpret_cast<const float4*>(&SHb[k0]);
            float4 s1 = *reinterpret_cast<const float4*>(&SHb[512 + k0]);
            float4 s2 = *reinterpret_cast<const float4*>(&SHb[1024 + k0]);
            float4 s3 = *reinterpret_cast<const float4*>(&SHb[1536 + k0]);
            #pragma unroll
            for (int j = 0; j < 4; ++j) {
                float4 w4 = __ldg(reinterpret_cast<const float4*>(&W[(k0 + j) * 32]));
                ull wlo = pk(w4.x, w4.y), whi = pk(w4.z, w4.w);
                float v0 = (&s0.x)[j], v1 = (&s1.x)[j];
                float v2 = (&s2.x)[j], v3 = (&s3.x)[j];
                fma2(acc[0][0], pk(v0, v0), wlo); fma2(acc[0][1], pk(v0, v0), whi);
                fma2(acc[1][0], pk(v1, v1), wlo); fma2(acc[1][1], pk(v1, v1), whi);
                fma2(acc[2][0], pk(v2, v2), wlo); fma2(acc[2][1], pk(v2, v2), whi);
                fma2(acc[3][0], pk(v3, v3), wlo); fma2(acc[3][1], pk(v3, v3), whi);
            }
        }
        #pragma unroll
        for (int p = 0; p < 4; ++p) {
            float2 v0 = unpk(acc[p][0]), v1 = unpk(acc[p][1]);
            *reinterpret_cast<float4*>(&sm[S_W1O + p * 256 + a * 32 + m0]) =
                make_float4(fabsf(v0.x), fabsf(v0.y), fabsf(v1.x), fabsf(v1.y));
        }
    }
    __syncthreads();

    // ===== hidden + final (fused, wf from S_WF); 4 pairs/thread =============
    if (t < 32) {
        int m = t;
        float part[4];
        #pragma unroll
        for (int p = 0; p < 4; ++p) {
            const float* AQ  = &sm[S_AQ + p * 8];
            const float* W1O = &sm[S_W1O + p * 256];
            float h = sm[S_HBP + p * 32 + m];
            #pragma unroll
            for (int a = 0; a < 8; ++a)
                h = fmaf(AQ[a], W1O[a * 32 + m], h);
            h = h > 0.f ? h : expm1f(h);
            part[p] = h * sm[S_WF + p * 32 + m]
                    + sm[S_H3 + p * 32 + m] * sm[OFF_VW2 + m];
        }
        #pragma unroll
        for (int p = 0; p < 4; ++p) {
            #pragma unroll
            for (int off = 16; off > 0; off >>= 1)
                part[p] += __shfl_down_sync(0xffffffffu, part[p], off);
        }
        if (m == 0) {
            float vb2 = sm[OFF_VB2];
            out[gp0 + 0] = part[0] + vb2;
            out[gp0 + 1] = part[1] + vb2;
            out[gp0 + 2] = part[2] + vb2;
            out[gp0 + 3] = part[3] + vb2;
        }
    }
}

extern "C" void kernel_launch(void* const* d_in, const int* in_sizes, int n_in,
                              void* d_out, int out_size) {
    (void)in_sizes; (void)n_in; (void)out_size;
    // inputs: 0 aq, 1 ally, 2 enemy, 3 W_al, 4 b_al, 5 W_en, 6 b_en,
    // 7 Wq, 8 bq, 9 Wk, 10 bk, 11 w1_W1, 12 w1_b1, 13 w1_W2, 14 w1_b2,
    // 15 wf_W1, 16 wf_b1, 17 wf_W2, 18 wf_b2, 19 hb_W, 20 hb_b,
    // 21 v_W1, 22 v_b1, 23 v_W2, 24 v_b2
    precompute1_kernel<<<16, 256>>>(
        (const float*)d_in[7], (const float*)d_in[9], (const float*)d_in[10]);
    precompute2_kernel<<<16, 256>>>(
        (const float*)d_in[3],  (const float*)d_in[4],
        (const float*)d_in[5],  (const float*)d_in[6],
        (const float*)d_in[11], (const float*)d_in[15],
        (const float*)d_in[19], (const float*)d_in[21]);
    cudaFuncSetAttribute(qmixer_kernel,
                         cudaFuncAttributeMaxDynamicSharedMemorySize, SMEM_BYTES);
    qmixer_kernel<<<GRID, NTH, SMEM_BYTES>>>(
        (const float*)d_in[0],  (const float*)d_in[1],  (const float*)d_in[2],
        (const float*)d_in[3],  (const float*)d_in[4],
        (const float*)d_in[5],  (const float*)d_in[6],
        (const float*)d_in[11], (const float*)d_in[12],
        (const float*)d_in[13], (const float*)d_in[14],
        (const float*)d_in[16],
        (const float*)d_in[17], (const float*)d_in[18],
        (const float*)d_in[20],
        (const float*)d_in[22],
        (const float*)d_in[23], (const float*)d_in[24],
        (float*)d_out);
}